// round 4
// baseline (speedup 1.0000x reference)
#include <cuda_runtime.h>
#include <math.h>

#define BB 4
#define CIN 64
#define HH 128
#define WW 128
#define HWSZ (HH*WW)
#define COUT 64
#define C27 27
#define CK 576  // CIN*9

// Scratch (device globals: no allocation allowed in kernel_launch)
__device__ __align__(16) float g_om[BB*C27*HWSZ];   // dy(0..8), dx(9..17), sigmoid(mask)(18..26)
__device__ __align__(16) float g_wT[CK*COUT];       // main weight: [k][c][64]
__device__ __align__(16) float g_owT[CK*28];        // offset weight: [c*9+k][28]

typedef unsigned long long u64;

__device__ __forceinline__ u64 pack2(float a, float b) {
    u64 r;
    asm("mov.b64 %0, {%1, %2};" : "=l"(r) : "f"(a), "f"(b));
    return r;
}
__device__ __forceinline__ void unpack2(u64 v, float& a, float& b) {
    asm("mov.b64 {%0, %1}, %2;" : "=f"(a), "=f"(b) : "l"(v));
}
__device__ __forceinline__ void ffma2(u64& d, u64 a, u64 b) {
    asm("fma.rn.f32x2 %0, %1, %2, %0;" : "+l"(d) : "l"(a), "l"(b));
}
__device__ __forceinline__ void cp_async16(void* smem_dst, const void* gsrc) {
    unsigned s = (unsigned)__cvta_generic_to_shared(smem_dst);
    asm volatile("cp.async.cg.shared.global [%0], [%1], 16;" :: "r"(s), "l"(gsrc));
}

// ---------------------------------------------------------------------------
// Kernel 0: weight transposes
// ---------------------------------------------------------------------------
__global__ void prep_kernel(const float* __restrict__ wt, const float* __restrict__ owt) {
    int idx = blockIdx.x * blockDim.x + threadIdx.x;
    if (idx < CK*COUT) {
        // dest layout [k][c][o]
        int o = idx & 63;
        int kc = idx >> 6;
        int k = kc / CIN;
        int c = kc - k * CIN;
        g_wT[idx] = wt[o*CK + c*9 + k];
    }
    if (idx < CK*28) {
        int o  = idx % 28;
        int ck = idx / 28;   // c*9+k
        g_owT[idx] = (o < C27) ? owt[o*CK + ck] : 0.f;
    }
}

// ---------------------------------------------------------------------------
// Kernel 1: offset/mask conv (3x3 pad1), 27 out ch. 1 px/thread, FFMA2,
// full offset-weight table staged in shared memory (63 KB).
// ---------------------------------------------------------------------------
__global__ __launch_bounds__(256) void offset_kernel(const float* __restrict__ x,
                                                     const float* __restrict__ ob) {
    __shared__ __align__(16) float sow[CK*28];   // 64512 B

    // cooperative stage: 4032 float4
    {
        const float4* src = (const float4*)g_owT;
        float4* dst = (float4*)sow;
        #pragma unroll 4
        for (int i = threadIdx.x; i < CK*28/4; i += 256) dst[i] = __ldg(src + i);
    }
    __syncthreads();

    int t  = blockIdx.x * 256 + threadIdx.x;
    int b  = t >> 14;
    int hw = t & (HWSZ - 1);
    int h  = hw >> 7;
    int w  = hw & 127;

    // packed accumulators: 14 x f32x2 (channels 2q, 2q+1)
    u64 acc[14];
    #pragma unroll
    for (int q = 0; q < 14; q++) {
        float b0 = __ldg(ob + 2*q);
        float b1 = (2*q + 1 < C27) ? __ldg(ob + 2*q + 1) : 0.f;
        acc[q] = pack2(b0, b1);
    }

    // neighbor indices with -1 sentinel (pixel-invariant over c)
    int nidx[9];
    #pragma unroll
    for (int kh = 0; kh < 3; kh++)
        #pragma unroll
        for (int kw = 0; kw < 3; kw++) {
            int hh = h - 1 + kh, ww = w - 1 + kw;
            nidx[kh*3+kw] = (hh >= 0 && hh < HH && ww >= 0 && ww < WW) ? hh*WW + ww : -1;
        }

    const float* xb = x + (size_t)b * CIN * HWSZ;
    #pragma unroll 1
    for (int c = 0; c < CIN; c++) {
        const float* xc = xb + c * HWSZ;
        float xv[9];
        #pragma unroll
        for (int k = 0; k < 9; k++) xv[k] = (nidx[k] >= 0) ? __ldg(xc + nidx[k]) : 0.f;
        #pragma unroll
        for (int k = 0; k < 9; k++) {
            u64 v = pack2(xv[k], xv[k]);
            const ulonglong2* wp = (const ulonglong2*)(sow + (c*9 + k) * 28);
            #pragma unroll
            for (int q = 0; q < 7; q++) {
                ulonglong2 ww = wp[q];
                ffma2(acc[2*q],   v, ww.x);
                ffma2(acc[2*q+1], v, ww.y);
            }
        }
    }

    float* om = g_om + (size_t)b * C27 * HWSZ + hw;
    #pragma unroll
    for (int q = 0; q < 14; q++) {
        float a0, a1;
        unpack2(acc[q], a0, a1);
        int o0 = 2*q, o1 = 2*q + 1;
        if (o0 >= 18) a0 = 1.f / (1.f + __expf(-a0));
        om[o0*HWSZ] = a0;
        if (o1 < C27) {
            if (o1 >= 18) a1 = 1.f / (1.f + __expf(-a1));
            om[o1*HWSZ] = a1;
        }
    }
}

// ---------------------------------------------------------------------------
// Kernel 2: deformable sampling + implicit GEMM. 1 px/thread, FFMA2,
// double-buffered per-k weight tiles via cp.async, gathers prefetched.
// ---------------------------------------------------------------------------
__global__ __launch_bounds__(256, 2) void dcn_kernel(const float* __restrict__ x,
                                                     const float* __restrict__ bias,
                                                     float* __restrict__ out) {
    __shared__ __align__(16) float sw[2][CIN*COUT];   // 2 x 16 KB

    int t  = blockIdx.x * 256 + threadIdx.x;
    int b  = t >> 14;
    int hw = t & (HWSZ - 1);
    int h  = hw >> 7;
    int w  = hw & 127;

    u64 acc[32];
    #pragma unroll
    for (int q = 0; q < 16; q++) {
        ulonglong2 bb = __ldg((const ulonglong2*)bias + q);
        acc[2*q] = bb.x;  acc[2*q+1] = bb.y;
    }

    const float* xb  = x + (size_t)b * CIN * HWSZ;
    const float* omb = g_om + (size_t)b * C27 * HWSZ + hw;

    // prologue: stage tile k=0 into buffer 0
    {
        const float* src = g_wT;
        #pragma unroll
        for (int i = 0; i < 4; i++) {
            int e = (threadIdx.x + i*256) * 4;
            cp_async16(&sw[0][e], src + e);
        }
        asm volatile("cp.async.commit_group;");
    }

    #pragma unroll 1
    for (int k = 0; k < 9; k++) {
        // all threads done reading buffer (k+1)&1 (tile k-1) before overwrite
        __syncthreads();
        if (k < 8) {
            const float* src = g_wT + (k+1) * CIN * COUT;
            float* dst = sw[(k+1) & 1];
            #pragma unroll
            for (int i = 0; i < 4; i++) {
                int e = (threadIdx.x + i*256) * 4;
                cp_async16(dst + e, src + e);
            }
            asm volatile("cp.async.commit_group;");
            asm volatile("cp.async.wait_group 1;");   // tile k landed
        } else {
            asm volatile("cp.async.wait_group 0;");
        }
        __syncthreads();

        int kh = k / 3, kw = k - kh*3;
        float dy = __ldg(omb + k*HWSZ);
        float dx = __ldg(omb + (9+k)*HWSZ);
        float m  = __ldg(omb + (18+k)*HWSZ);
        float hh = (float)(h - 1 + kh) + dy;
        float ww = (float)(w - 1 + kw) + dx;
        float h0f = floorf(hh), w0f = floorf(ww);
        float lh = hh - h0f, lw = ww - w0f;
        int h0 = (int)h0f, w0 = (int)w0f, h1 = h0+1, w1 = w0+1;
        bool vh0 = (h0>=0)&&(h0<HH), vh1 = (h1>=0)&&(h1<HH);
        bool vw0 = (w0>=0)&&(w0<WW), vw1 = (w1>=0)&&(w1<WW);
        int ch0 = min(max(h0,0),HH-1), ch1 = min(max(h1,0),HH-1);
        int cw0 = min(max(w0,0),WW-1), cw1 = min(max(w1,0),WW-1);
        int i00 = ch0*WW+cw0, i01 = ch0*WW+cw1;
        int i10 = ch1*WW+cw0, i11 = ch1*WW+cw1;
        float w00 = (1.f-lh)*(1.f-lw)*m*((vh0&&vw0)?1.f:0.f);
        float w01 = (1.f-lh)*lw      *m*((vh0&&vw1)?1.f:0.f);
        float w10 = lh*(1.f-lw)      *m*((vh1&&vw0)?1.f:0.f);
        float w11 = lh*lw            *m*((vh1&&vw1)?1.f:0.f);

        const float* swk = sw[k & 1];

        // peeled pipeline: prefetch c=0 gathers
        float v00 = __ldg(xb + i00), v01 = __ldg(xb + i01);
        float v10 = __ldg(xb + i10), v11 = __ldg(xb + i11);

        const float* xc = xb;
        #pragma unroll 2
        for (int c = 0; c < CIN-1; c++) {
            const float* xn = xc + HWSZ;
            float n00 = __ldg(xn + i00), n01 = __ldg(xn + i01);
            float n10 = __ldg(xn + i10), n11 = __ldg(xn + i11);
            float val = w00 * v00;
            val = fmaf(w01, v01, val);
            val = fmaf(w10, v10, val);
            val = fmaf(w11, v11, val);
            u64 v = pack2(val, val);
            const ulonglong2* wp = (const ulonglong2*)(swk + c * COUT);
            #pragma unroll
            for (int q = 0; q < 16; q++) {
                ulonglong2 wv = wp[q];
                ffma2(acc[2*q],   v, wv.x);
                ffma2(acc[2*q+1], v, wv.y);
            }
            v00 = n00; v01 = n01; v10 = n10; v11 = n11;
            xc = xn;
        }
        {   // last channel
            float val = w00 * v00;
            val = fmaf(w01, v01, val);
            val = fmaf(w10, v10, val);
            val = fmaf(w11, v11, val);
            u64 v = pack2(val, val);
            const ulonglong2* wp = (const ulonglong2*)(swk + (CIN-1) * COUT);
            #pragma unroll
            for (int q = 0; q < 16; q++) {
                ulonglong2 wv = wp[q];
                ffma2(acc[2*q],   v, wv.x);
                ffma2(acc[2*q+1], v, wv.y);
            }
        }
    }

    float* ob = out + (size_t)b * COUT * HWSZ + hw;
    #pragma unroll
    for (int q = 0; q < 32; q++) {
        float a0, a1;
        unpack2(acc[q], a0, a1);
        ob[(2*q)*HWSZ]   = a0;
        ob[(2*q+1)*HWSZ] = a1;
    }
}

// ---------------------------------------------------------------------------
extern "C" void kernel_launch(void* const* d_in, const int* in_sizes, int n_in,
                              void* d_out, int out_size) {
    const float* x    = (const float*)d_in[0];  // [4,64,128,128]
    const float* wt   = (const float*)d_in[1];  // [64,64,3,3]
    const float* bias = (const float*)d_in[2];  // [64]
    const float* owt  = (const float*)d_in[3];  // [27,64,3,3]
    const float* ob   = (const float*)d_in[4];  // [27]
    float* out = (float*)d_out;                 // [4,64,128,128]

    prep_kernel<<<(CK*COUT + 255) / 256, 256>>>(wt, owt);
    offset_kernel<<<BB*HWSZ/256, 256>>>(x, ob);
    dcn_kernel<<<BB*HWSZ/256, 256>>>(x, bias, out);
}

// round 6
// speedup vs baseline: 1.6703x; 1.6703x over previous
#include <cuda_runtime.h>
#include <cuda_bf16.h>
#include <math.h>
#include <stdint.h>

#define BB 4
#define CIN 64
#define HH 128
#define WW 128
#define HWSZ (HH*WW)
#define COUT 64
#define C27 27
#define CK 576  // CIN*9

// ---------------- device scratch (no allocs allowed) ----------------
__device__ __align__(16) float g_om[BB*C27*HWSZ];        // offset-conv out
__device__ __align__(16) float g_owT[CK*28];             // offset weights [ck][28]
// main-conv B operand per tap: [k][oc 64][c 64] bf16 hi/lo, 8KB per tap each
__device__ __align__(16) __nv_bfloat16 g_wBh[9*4096];
__device__ __align__(16) __nv_bfloat16 g_wBl[9*4096];

typedef unsigned long long u64;

// ---------------- helpers ----------------
__device__ __forceinline__ uint32_t smem_u32(const void* p) {
    uint32_t a;
    asm("{ .reg .u64 t; cvta.to.shared.u64 t, %1; cvt.u32.u64 %0, t; }" : "=r"(a) : "l"(p));
    return a;
}
__device__ __forceinline__ u64 pack2(float a, float b) {
    u64 r; asm("mov.b64 %0, {%1, %2};" : "=l"(r) : "f"(a), "f"(b)); return r;
}
__device__ __forceinline__ void unpack2(u64 v, float& a, float& b) {
    asm("mov.b64 {%0, %1}, %2;" : "=f"(a), "=f"(b) : "l"(v));
}
__device__ __forceinline__ void ffma2(u64& d, u64 a, u64 b) {
    asm("fma.rn.f32x2 %0, %1, %2, %0;" : "+l"(d) : "l"(a), "l"(b));
}
__device__ __forceinline__ void cp_async16(uint32_t smem_dst, const void* gsrc) {
    asm volatile("cp.async.cg.shared.global [%0], [%1], 16;" :: "r"(smem_dst), "l"(gsrc));
}
__device__ __forceinline__ void sts128(uint32_t addr, uint32_t r0, uint32_t r1, uint32_t r2, uint32_t r3) {
    asm volatile("st.shared.v4.b32 [%0], {%1, %2, %3, %4};" :: "r"(addr), "r"(r0), "r"(r1), "r"(r2), "r"(r3) : "memory");
}
__device__ __forceinline__ void ldsm4(uint32_t a, uint32_t& r0, uint32_t& r1, uint32_t& r2, uint32_t& r3) {
    asm volatile("ldmatrix.sync.aligned.m8n8.x4.shared.b16 {%0,%1,%2,%3}, [%4];"
                 : "=r"(r0), "=r"(r1), "=r"(r2), "=r"(r3) : "r"(a));
}
__device__ __forceinline__ void mma16816(float* d, const uint32_t* a, const uint32_t* b) {
    asm volatile("mma.sync.aligned.m16n8k16.row.col.f32.bf16.bf16.f32 "
                 "{%0,%1,%2,%3}, {%4,%5,%6,%7}, {%8,%9}, {%0,%1,%2,%3};"
                 : "+f"(d[0]), "+f"(d[1]), "+f"(d[2]), "+f"(d[3])
                 : "r"(a[0]), "r"(a[1]), "r"(a[2]), "r"(a[3]), "r"(b[0]), "r"(b[1]));
}

// ---------------------------------------------------------------------------
// Kernel 0: weight prep.
//  - offset weights -> [ck][28] table
//  - main weights   -> per-tap B tiles [oc][c] bf16 hi/lo
// ---------------------------------------------------------------------------
__global__ void prep_kernel(const float* __restrict__ wt, const float* __restrict__ owt) {
    int idx = blockIdx.x * blockDim.x + threadIdx.x;    // grid covers 36864
    if (idx < 9*4096) {
        int k  = idx >> 12;
        int oc = (idx >> 6) & 63;
        int c  = idx & 63;
        float w = wt[oc*CK + c*9 + k];
        uint32_t wb = __float_as_uint(w);
        uint32_t hib = wb & 0xFFFF0000u;
        float lo = w - __uint_as_float(hib);
        int d = k*4096 + oc*64 + c;
        ((uint16_t*)g_wBh)[d] = (uint16_t)(hib >> 16);
        g_wBl[d] = __float2bfloat16(lo);
    }
    if (idx < CK*28) {
        int o  = idx % 28;
        int ck = idx / 28;
        g_owT[idx] = (o < C27) ? owt[o*CK + ck] : 0.f;
    }
}

// ---------------------------------------------------------------------------
// Kernel 1: offset/mask conv (3x3 pad1), 27 out ch. 1 px/thread, FFMA2,
// full offset-weight table staged in shared memory. (unchanged, known good)
// ---------------------------------------------------------------------------
__global__ __launch_bounds__(256) void offset_kernel(const float* __restrict__ x,
                                                     const float* __restrict__ ob) {
    __shared__ __align__(16) float sow[CK*28];

    {
        const float4* src = (const float4*)g_owT;
        float4* dst = (float4*)sow;
        #pragma unroll 4
        for (int i = threadIdx.x; i < CK*28/4; i += 256) dst[i] = __ldg(src + i);
    }
    __syncthreads();

    int t  = blockIdx.x * 256 + threadIdx.x;
    int b  = t >> 14;
    int hw = t & (HWSZ - 1);
    int h  = hw >> 7;
    int w  = hw & 127;

    u64 acc[14];
    #pragma unroll
    for (int q = 0; q < 14; q++) {
        float b0 = __ldg(ob + 2*q);
        float b1 = (2*q + 1 < C27) ? __ldg(ob + 2*q + 1) : 0.f;
        acc[q] = pack2(b0, b1);
    }

    int nidx[9];
    #pragma unroll
    for (int kh = 0; kh < 3; kh++)
        #pragma unroll
        for (int kw = 0; kw < 3; kw++) {
            int hh = h - 1 + kh, ww = w - 1 + kw;
            nidx[kh*3+kw] = (hh >= 0 && hh < HH && ww >= 0 && ww < WW) ? hh*WW + ww : -1;
        }

    const float* xb = x + (size_t)b * CIN * HWSZ;
    #pragma unroll 1
    for (int c = 0; c < CIN; c++) {
        const float* xc = xb + c * HWSZ;
        float xv[9];
        #pragma unroll
        for (int k = 0; k < 9; k++) xv[k] = (nidx[k] >= 0) ? __ldg(xc + nidx[k]) : 0.f;
        #pragma unroll
        for (int k = 0; k < 9; k++) {
            u64 v = pack2(xv[k], xv[k]);
            const ulonglong2* wp = (const ulonglong2*)(sow + (c*9 + k) * 28);
            #pragma unroll
            for (int q = 0; q < 7; q++) {
                ulonglong2 ww = wp[q];
                ffma2(acc[2*q],   v, ww.x);
                ffma2(acc[2*q+1], v, ww.y);
            }
        }
    }

    float* om = g_om + (size_t)b * C27 * HWSZ + hw;
    #pragma unroll
    for (int q = 0; q < 14; q++) {
        float a0, a1;
        unpack2(acc[q], a0, a1);
        int o0 = 2*q, o1 = 2*q + 1;
        if (o0 >= 18) a0 = 1.f / (1.f + __expf(-a0));
        om[o0*HWSZ] = a0;
        if (o1 < C27) {
            if (o1 >= 18) a1 = 1.f / (1.f + __expf(-a1));
            om[o1*HWSZ] = a1;
        }
    }
}

// ---------------------------------------------------------------------------
// Kernel 2: deformable conv via mma.sync bf16 3-pass split GEMM.
// CTA = 128 px (one image row) x 64 oc, 256 threads = 8 warps.
// Warp w owns px rows 16w..16w+15, all 64 oc; f32 register accumulators.
// Per tap: stage B hi/lo (cp.async, overlapped), produce A hi/lo (bilinear
// im2col) into 144B-pitch smem, then 4 k-steps x 24 mma.m16n8k16.
// ---------------------------------------------------------------------------
#define PITCH   144
#define SM_A_HI 0
#define SM_A_LO 18432
#define SM_B_HI 36864
#define SM_B_LO 46080
#define SM_TOT  55296

__global__ __launch_bounds__(256, 2) void dcn_mma_kernel(const float* __restrict__ x,
                                                         const float* __restrict__ bias,
                                                         float* __restrict__ out) {
    extern __shared__ __align__(16) char smem[];
    uint32_t sb = smem_u32(smem);
    int tid  = threadIdx.x;
    int lane = tid & 31, wid = tid >> 5;
    int b  = blockIdx.x >> 7;
    int h  = blockIdx.x & 127;
    int px = tid & 127;
    int c0 = (tid >> 7) * 32;
    int hw = (h << 7) + px;

    float acc[8][4] = {};

    const float* xb  = x + (size_t)b * CIN * HWSZ;
    const float* omb = g_om + (size_t)b * C27 * HWSZ + hw;

    // ldmatrix lane-address components
    int seg = lane >> 3, r8 = lane & 7;
    int m0  = wid * 16;
    uint32_t aBaseH = sb + SM_A_HI + (uint32_t)((m0 + (seg&1)*8 + r8) * PITCH + (seg>>1)*16);
    uint32_t aBaseL = aBaseH + (SM_A_LO - SM_A_HI);
    uint32_t bColB  = (uint32_t)((seg&1)*16);
    uint32_t bRowB  = (uint32_t)(((seg>>1)*8 + r8) * PITCH);

    #pragma unroll 1
    for (int k = 0; k < 9; k++) {
        // ---- stage B tiles (hi+lo, 1024 x 16B chunks) ----
        #pragma unroll
        for (int i = 0; i < 4; i++) {
            int e   = tid + i*256;            // 0..1023
            int t8  = e >> 9;                 // 0 = hi, 1 = lo
            int cnk = e & 511;
            int row = cnk >> 3, c16 = (cnk & 7) * 16;
            const char* src = (t8 ? (const char*)g_wBl : (const char*)g_wBh)
                              + (size_t)k*8192 + row*128 + c16;
            uint32_t dst = sb + (t8 ? SM_B_LO : SM_B_HI) + (uint32_t)(row*PITCH + c16);
            cp_async16(dst, src);
        }
        asm volatile("cp.async.commit_group;");

        // ---- bilinear params for (px, tap) ----
        int kh = k / 3, kw = k - kh*3;
        float dy = __ldg(omb + k*HWSZ);
        float dx = __ldg(omb + (9+k)*HWSZ);
        float m  = __ldg(omb + (18+k)*HWSZ);
        float hh = (float)(h - 1 + kh) + dy;
        float ww = (float)(px - 1 + kw) + dx;
        float h0f = floorf(hh), w0f = floorf(ww);
        float lh = hh - h0f, lw = ww - w0f;
        int h0 = (int)h0f, w0 = (int)w0f, h1 = h0+1, w1 = w0+1;
        bool vh0 = (h0>=0)&&(h0<HH), vh1 = (h1>=0)&&(h1<HH);
        bool vw0 = (w0>=0)&&(w0<WW), vw1 = (w1>=0)&&(w1<WW);
        int ch0 = min(max(h0,0),HH-1), ch1 = min(max(h1,0),HH-1);
        int cw0 = min(max(w0,0),WW-1), cw1 = min(max(w1,0),WW-1);
        int i00 = ch0*WW+cw0, i01 = ch0*WW+cw1;
        int i10 = ch1*WW+cw0, i11 = ch1*WW+cw1;
        float w00 = (1.f-lh)*(1.f-lw)*m*((vh0&&vw0)?1.f:0.f);
        float w01 = (1.f-lh)*lw      *m*((vh0&&vw1)?1.f:0.f);
        float w10 = lh*(1.f-lw)      *m*((vh1&&vw0)?1.f:0.f);
        float w11 = lh*lw            *m*((vh1&&vw1)?1.f:0.f);

        // ---- produce A tile: this thread covers c0..c0+31 for its px ----
        #pragma unroll 1
        for (int g = 0; g < 4; g++) {
            int cc = c0 + g*8;
            const float* xc = xb + (size_t)cc * HWSZ;
            float v[8];
            #pragma unroll
            for (int j = 0; j < 8; j++) {
                const float* xp = xc + (size_t)j * HWSZ;
                float t = w00 * __ldg(xp + i00);
                t = fmaf(w01, __ldg(xp + i01), t);
                t = fmaf(w10, __ldg(xp + i10), t);
                t = fmaf(w11, __ldg(xp + i11), t);
                v[j] = t;
            }
            uint32_t hi[4], lo[4];
            #pragma unroll
            for (int j = 0; j < 4; j++) {
                uint32_t b0 = __float_as_uint(v[2*j])   & 0xFFFF0000u;
                uint32_t b1 = __float_as_uint(v[2*j+1]) & 0xFFFF0000u;
                hi[j] = (b0 >> 16) | b1;
                float l0 = v[2*j]   - __uint_as_float(b0);
                float l1 = v[2*j+1] - __uint_as_float(b1);
                asm("cvt.rn.bf16x2.f32 %0, %1, %2;" : "=r"(lo[j]) : "f"(l1), "f"(l0));
            }
            uint32_t off = (uint32_t)(px*PITCH + cc*2);
            sts128(sb + SM_A_HI + off, hi[0], hi[1], hi[2], hi[3]);
            sts128(sb + SM_A_LO + off, lo[0], lo[1], lo[2], lo[3]);
        }

        asm volatile("cp.async.wait_group 0;");
        __syncthreads();

        // ---- MMA: 4 k-steps x (2 A-ldsm + 8 B-ldsm + 24 mma) ----
        #pragma unroll
        for (int ks = 0; ks < 4; ks++) {
            uint32_t ah[4], al[4];
            ldsm4(aBaseH + ks*32, ah[0], ah[1], ah[2], ah[3]);
            ldsm4(aBaseL + ks*32, al[0], al[1], al[2], al[3]);
            uint32_t bh[8][2], bl[8][2];
            #pragma unroll
            for (int q = 0; q < 4; q++) {
                uint32_t ra = sb + bRowB + (uint32_t)(q*16*PITCH) + bColB + ks*32;
                ldsm4(ra + SM_B_HI, bh[2*q][0], bh[2*q][1], bh[2*q+1][0], bh[2*q+1][1]);
                ldsm4(ra + SM_B_LO, bl[2*q][0], bl[2*q][1], bl[2*q+1][0], bl[2*q+1][1]);
            }
            #pragma unroll
            for (int nc = 0; nc < 8; nc++) {
                mma16816(acc[nc], ah, bh[nc]);
                mma16816(acc[nc], ah, bl[nc]);
                mma16816(acc[nc], al, bh[nc]);
            }
        }
        __syncthreads();   // A/B consumed; safe to overwrite next tap
    }

    // ---- epilogue: lane l holds D(m = m0 + l/4 (+8), n = nc*8 + 2*(l%4)+{0,1}) ----
    {
        int ml = m0 + (lane >> 2);
        int nf = (lane & 3) * 2;
        float* ob = out + (size_t)b * COUT * HWSZ + (h << 7) + ml;
        #pragma unroll
        for (int nc = 0; nc < 8; nc++) {
            int n = nc*8 + nf;
            float b0 = __ldg(bias + n), b1 = __ldg(bias + n + 1);
            ob[(size_t)n*HWSZ]           = acc[nc][0] + b0;
            ob[(size_t)(n+1)*HWSZ]       = acc[nc][1] + b1;
            ob[(size_t)n*HWSZ + 8]       = acc[nc][2] + b0;
            ob[(size_t)(n+1)*HWSZ + 8]   = acc[nc][3] + b1;
        }
    }
}

// ---------------------------------------------------------------------------
extern "C" void kernel_launch(void* const* d_in, const int* in_sizes, int n_in,
                              void* d_out, int out_size) {
    const float* x    = (const float*)d_in[0];  // [4,64,128,128]
    const float* wt   = (const float*)d_in[1];  // [64,64,3,3]
    const float* bias = (const float*)d_in[2];  // [64]
    const float* owt  = (const float*)d_in[3];  // [27,64,3,3]
    const float* ob   = (const float*)d_in[4];  // [27]
    float* out = (float*)d_out;                 // [4,64,128,128]

    cudaFuncSetAttribute(dcn_mma_kernel, cudaFuncAttributeMaxDynamicSharedMemorySize, SM_TOT);

    prep_kernel<<<144, 256>>>(wt, owt);
    offset_kernel<<<BB*HWSZ/256, 256>>>(x, ob);
    dcn_mma_kernel<<<512, 256, SM_TOT>>>(x, bias, out);
}

// round 7
// speedup vs baseline: 2.2024x; 1.3186x over previous
#include <cuda_runtime.h>
#include <cuda_bf16.h>
#include <math.h>
#include <stdint.h>

#define BB 4
#define CIN 64
#define HH 128
#define WW 128
#define HWSZ (HH*WW)
#define COUT 64
#define C27 27
#define CK 576  // CIN*9

// ---------------- device scratch (no allocs allowed) ----------------
__device__ __align__(16) float g_om[BB*C27*HWSZ];        // offset-conv out
// main-conv B per tap: [k][oc 64][c 64] bf16 hi/lo
__device__ __align__(16) __nv_bfloat16 g_wBh[9*4096];
__device__ __align__(16) __nv_bfloat16 g_wBl[9*4096];
// offset-conv B per tap: [k][oc 32 (27 padded)][c 64] bf16 hi/lo
__device__ __align__(16) __nv_bfloat16 g_oBh[9*2048];
__device__ __align__(16) __nv_bfloat16 g_oBl[9*2048];

typedef unsigned long long u64;

// ---------------- helpers ----------------
__device__ __forceinline__ uint32_t smem_u32(const void* p) {
    uint32_t a;
    asm("{ .reg .u64 t; cvta.to.shared.u64 t, %1; cvt.u32.u64 %0, t; }" : "=r"(a) : "l"(p));
    return a;
}
__device__ __forceinline__ void cp_async16(uint32_t smem_dst, const void* gsrc) {
    asm volatile("cp.async.cg.shared.global [%0], [%1], 16;" :: "r"(smem_dst), "l"(gsrc));
}
__device__ __forceinline__ void sts128(uint32_t addr, uint32_t r0, uint32_t r1, uint32_t r2, uint32_t r3) {
    asm volatile("st.shared.v4.b32 [%0], {%1, %2, %3, %4};" :: "r"(addr), "r"(r0), "r"(r1), "r"(r2), "r"(r3) : "memory");
}
__device__ __forceinline__ void ldsm4(uint32_t a, uint32_t& r0, uint32_t& r1, uint32_t& r2, uint32_t& r3) {
    asm volatile("ldmatrix.sync.aligned.m8n8.x4.shared.b16 {%0,%1,%2,%3}, [%4];"
                 : "=r"(r0), "=r"(r1), "=r"(r2), "=r"(r3) : "r"(a));
}
__device__ __forceinline__ void mma16816(float* d, const uint32_t* a, const uint32_t* b) {
    asm volatile("mma.sync.aligned.m16n8k16.row.col.f32.bf16.bf16.f32 "
                 "{%0,%1,%2,%3}, {%4,%5,%6,%7}, {%8,%9}, {%0,%1,%2,%3};"
                 : "+f"(d[0]), "+f"(d[1]), "+f"(d[2]), "+f"(d[3])
                 : "r"(a[0]), "r"(a[1]), "r"(a[2]), "r"(a[3]), "r"(b[0]), "r"(b[1]));
}
// split f32 pair -> bf16x2 hi (truncate) + bf16x2 lo (residual, rounded)
__device__ __forceinline__ void split2(float v0, float v1, uint32_t& hi, uint32_t& lo) {
    uint32_t b0 = __float_as_uint(v0) & 0xFFFF0000u;
    uint32_t b1 = __float_as_uint(v1) & 0xFFFF0000u;
    hi = (b0 >> 16) | b1;
    float l0 = v0 - __uint_as_float(b0);
    float l1 = v1 - __uint_as_float(b1);
    asm("cvt.rn.bf16x2.f32 %0, %1, %2;" : "=r"(lo) : "f"(l1), "f"(l0));
}

#define PITCH 144

// ---------------------------------------------------------------------------
// Kernel 0: weight prep -> bf16 hi/lo B tiles for both convs
// ---------------------------------------------------------------------------
__global__ void prep_kernel(const float* __restrict__ wt, const float* __restrict__ owt) {
    int idx = blockIdx.x * blockDim.x + threadIdx.x;    // 144*256 = 36864
    if (idx < 9*4096) {
        int k  = idx >> 12;
        int oc = (idx >> 6) & 63;
        int c  = idx & 63;
        float w = wt[oc*CK + c*9 + k];
        uint32_t wb  = __float_as_uint(w);
        uint32_t hib = wb & 0xFFFF0000u;
        int d = k*4096 + oc*64 + c;
        ((uint16_t*)g_wBh)[d] = (uint16_t)(hib >> 16);
        g_wBl[d] = __float2bfloat16(w - __uint_as_float(hib));
    }
    if (idx < 9*2048) {
        int k  = idx >> 11;
        int oc = (idx >> 6) & 31;
        int c  = idx & 63;
        float w = (oc < C27) ? owt[oc*CK + c*9 + k] : 0.f;
        uint32_t wb  = __float_as_uint(w);
        uint32_t hib = wb & 0xFFFF0000u;
        int d = k*2048 + oc*64 + c;
        ((uint16_t*)g_oBh)[d] = (uint16_t)(hib >> 16);
        g_oBl[d] = __float2bfloat16(w - __uint_as_float(hib));
    }
}

// ---------------------------------------------------------------------------
// Kernel 1: offset/mask conv via mma.sync bf16 3-pass split GEMM.
// CTA = 128 px (one image row) x 32 oc (27 real), 256 threads = 8 warps.
// Per tap: A[128px][64c] = shifted x row (coalesced), B staged via cp.async.
// ---------------------------------------------------------------------------
#define OSM_A_HI 0
#define OSM_A_LO 18432
#define OSM_B    36864     // hi tile 32*144, then lo tile 32*144
#define OSM_TOT  46080

__global__ __launch_bounds__(256) void offset_mma_kernel(const float* __restrict__ x,
                                                         const float* __restrict__ ob) {
    extern __shared__ __align__(16) char smem[];
    uint32_t sb = smem_u32(smem);
    int tid  = threadIdx.x;
    int lane = tid & 31, wid = tid >> 5;
    int b  = blockIdx.x >> 7;
    int h  = blockIdx.x & 127;
    int px = tid & 127;
    int c0 = (tid >> 7) * 32;

    float acc[4][4] = {};

    const float* xb = x + (size_t)b * CIN * HWSZ;

    int seg = lane >> 3, r8 = lane & 7;
    int m0  = wid * 16;
    uint32_t aBaseH = sb + OSM_A_HI + (uint32_t)((m0 + (seg&1)*8 + r8) * PITCH + (seg>>1)*16);
    uint32_t aBaseL = aBaseH + (OSM_A_LO - OSM_A_HI);
    uint32_t bColB  = (uint32_t)((seg&1)*16);
    uint32_t bRowB  = (uint32_t)(((seg>>1)*8 + r8) * PITCH);

    #pragma unroll 1
    for (int k = 0; k < 9; k++) {
        // ---- stage B tile (hi 256 + lo 256 chunks of 16B) ----
        #pragma unroll
        for (int i = 0; i < 2; i++) {
            int e   = tid + i*256;
            int t8  = e >> 8;
            int cnk = e & 255;
            int row = cnk >> 3, c16 = (cnk & 7) * 16;
            const char* src = (t8 ? (const char*)g_oBl : (const char*)g_oBh)
                              + (size_t)k*4096 + row*128 + c16;
            uint32_t dst = sb + OSM_B + (uint32_t)(t8*4608 + row*PITCH + c16);
            cp_async16(dst, src);
        }
        asm volatile("cp.async.commit_group;");

        // ---- A production: plain shifted row, coalesced ----
        int kh = k / 3, kw = k - kh*3;
        int hs = h - 1 + kh;
        int ws = px - 1 + kw;
        bool valid = (hs >= 0) && (hs < HH) && (ws >= 0) && (ws < WW);
        const float* xs = xb + hs*WW + ws;
        #pragma unroll
        for (int g = 0; g < 4; g++) {
            int cc = c0 + g*8;
            float v[8];
            #pragma unroll
            for (int j = 0; j < 8; j++)
                v[j] = valid ? __ldg(xs + (size_t)(cc+j) * HWSZ) : 0.f;
            uint32_t hi[4], lo[4];
            #pragma unroll
            for (int j = 0; j < 4; j++) split2(v[2*j], v[2*j+1], hi[j], lo[j]);
            uint32_t off = (uint32_t)(px*PITCH + cc*2);
            sts128(sb + OSM_A_HI + off, hi[0], hi[1], hi[2], hi[3]);
            sts128(sb + OSM_A_LO + off, lo[0], lo[1], lo[2], lo[3]);
        }

        asm volatile("cp.async.wait_group 0;");
        __syncthreads();

        // ---- MMA: 4 ks x (2 A-ldsm + 4 B-ldsm + 12 mma) ----
        #pragma unroll
        for (int ks = 0; ks < 4; ks++) {
            uint32_t ah[4], al[4];
            ldsm4(aBaseH + ks*32, ah[0], ah[1], ah[2], ah[3]);
            ldsm4(aBaseL + ks*32, al[0], al[1], al[2], al[3]);
            uint32_t bh[4][2], bl[4][2];
            #pragma unroll
            for (int q = 0; q < 2; q++) {
                uint32_t ra = sb + OSM_B + bRowB + (uint32_t)(q*16*PITCH) + bColB + ks*32;
                ldsm4(ra,        bh[2*q][0], bh[2*q][1], bh[2*q+1][0], bh[2*q+1][1]);
                ldsm4(ra + 4608, bl[2*q][0], bl[2*q][1], bl[2*q+1][0], bl[2*q+1][1]);
            }
            #pragma unroll
            for (int nc = 0; nc < 4; nc++) {
                mma16816(acc[nc], ah, bh[nc]);
                mma16816(acc[nc], ah, bl[nc]);
                mma16816(acc[nc], al, bh[nc]);
            }
        }
        __syncthreads();
    }

    // ---- epilogue: bias + sigmoid(mask rows), store to g_om ----
    {
        int ml = m0 + (lane >> 2);
        int nf = (lane & 3) * 2;
        float* om = g_om + (size_t)b * C27 * HWSZ + (h << 7) + ml;
        #pragma unroll
        for (int nc = 0; nc < 4; nc++) {
            int n = nc*8 + nf;
            #pragma unroll
            for (int half = 0; half < 2; half++) {
                int nn = n + half;
                if (nn < C27) {
                    float v0 = acc[nc][half]     + __ldg(ob + nn);   // m = ml
                    float v1 = acc[nc][half + 2] + __ldg(ob + nn);   // m = ml+8
                    if (nn >= 18) {
                        v0 = 1.f / (1.f + __expf(-v0));
                        v1 = 1.f / (1.f + __expf(-v1));
                    }
                    om[(size_t)nn*HWSZ]     = v0;
                    om[(size_t)nn*HWSZ + 8] = v1;
                }
            }
        }
    }
}

// ---------------------------------------------------------------------------
// Kernel 2: deformable conv via mma.sync bf16 3-pass split GEMM. (R6, known good)
// ---------------------------------------------------------------------------
#define SM_A_HI 0
#define SM_A_LO 18432
#define SM_B_HI 36864
#define SM_B_LO 46080
#define SM_TOT  55296

__global__ __launch_bounds__(256, 2) void dcn_mma_kernel(const float* __restrict__ x,
                                                         const float* __restrict__ bias,
                                                         float* __restrict__ out) {
    extern __shared__ __align__(16) char smem[];
    uint32_t sb = smem_u32(smem);
    int tid  = threadIdx.x;
    int lane = tid & 31, wid = tid >> 5;
    int b  = blockIdx.x >> 7;
    int h  = blockIdx.x & 127;
    int px = tid & 127;
    int c0 = (tid >> 7) * 32;
    int hw = (h << 7) + px;

    float acc[8][4] = {};

    const float* xb  = x + (size_t)b * CIN * HWSZ;
    const float* omb = g_om + (size_t)b * C27 * HWSZ + hw;

    int seg = lane >> 3, r8 = lane & 7;
    int m0  = wid * 16;
    uint32_t aBaseH = sb + SM_A_HI + (uint32_t)((m0 + (seg&1)*8 + r8) * PITCH + (seg>>1)*16);
    uint32_t aBaseL = aBaseH + (SM_A_LO - SM_A_HI);
    uint32_t bColB  = (uint32_t)((seg&1)*16);
    uint32_t bRowB  = (uint32_t)(((seg>>1)*8 + r8) * PITCH);

    #pragma unroll 1
    for (int k = 0; k < 9; k++) {
        // ---- stage B tiles (hi+lo, 1024 x 16B chunks) ----
        #pragma unroll
        for (int i = 0; i < 4; i++) {
            int e   = tid + i*256;
            int t8  = e >> 9;
            int cnk = e & 511;
            int row = cnk >> 3, c16 = (cnk & 7) * 16;
            const char* src = (t8 ? (const char*)g_wBl : (const char*)g_wBh)
                              + (size_t)k*8192 + row*128 + c16;
            uint32_t dst = sb + (t8 ? SM_B_LO : SM_B_HI) + (uint32_t)(row*PITCH + c16);
            cp_async16(dst, src);
        }
        asm volatile("cp.async.commit_group;");

        // ---- bilinear params ----
        int kh = k / 3, kw = k - kh*3;
        float dy = __ldg(omb + k*HWSZ);
        float dx = __ldg(omb + (9+k)*HWSZ);
        float m  = __ldg(omb + (18+k)*HWSZ);
        float hh = (float)(h - 1 + kh) + dy;
        float ww = (float)(px - 1 + kw) + dx;
        float h0f = floorf(hh), w0f = floorf(ww);
        float lh = hh - h0f, lw = ww - w0f;
        int h0 = (int)h0f, w0 = (int)w0f, h1 = h0+1, w1 = w0+1;
        bool vh0 = (h0>=0)&&(h0<HH), vh1 = (h1>=0)&&(h1<HH);
        bool vw0 = (w0>=0)&&(w0<WW), vw1 = (w1>=0)&&(w1<WW);
        int ch0 = min(max(h0,0),HH-1), ch1 = min(max(h1,0),HH-1);
        int cw0 = min(max(w0,0),WW-1), cw1 = min(max(w1,0),WW-1);
        int i00 = ch0*WW+cw0, i01 = ch0*WW+cw1;
        int i10 = ch1*WW+cw0, i11 = ch1*WW+cw1;
        float w00 = (1.f-lh)*(1.f-lw)*m*((vh0&&vw0)?1.f:0.f);
        float w01 = (1.f-lh)*lw      *m*((vh0&&vw1)?1.f:0.f);
        float w10 = lh*(1.f-lw)      *m*((vh1&&vw0)?1.f:0.f);
        float w11 = lh*lw            *m*((vh1&&vw1)?1.f:0.f);

        // ---- produce A tile ----
        #pragma unroll 1
        for (int g = 0; g < 4; g++) {
            int cc = c0 + g*8;
            const float* xc = xb + (size_t)cc * HWSZ;
            float v[8];
            #pragma unroll
            for (int j = 0; j < 8; j++) {
                const float* xp = xc + (size_t)j * HWSZ;
                float t = w00 * __ldg(xp + i00);
                t = fmaf(w01, __ldg(xp + i01), t);
                t = fmaf(w10, __ldg(xp + i10), t);
                t = fmaf(w11, __ldg(xp + i11), t);
                v[j] = t;
            }
            uint32_t hi[4], lo[4];
            #pragma unroll
            for (int j = 0; j < 4; j++) split2(v[2*j], v[2*j+1], hi[j], lo[j]);
            uint32_t off = (uint32_t)(px*PITCH + cc*2);
            sts128(sb + SM_A_HI + off, hi[0], hi[1], hi[2], hi[3]);
            sts128(sb + SM_A_LO + off, lo[0], lo[1], lo[2], lo[3]);
        }

        asm volatile("cp.async.wait_group 0;");
        __syncthreads();

        // ---- MMA: 4 ks x (2 A-ldsm + 8 B-ldsm + 24 mma) ----
        #pragma unroll
        for (int ks = 0; ks < 4; ks++) {
            uint32_t ah[4], al[4];
            ldsm4(aBaseH + ks*32, ah[0], ah[1], ah[2], ah[3]);
            ldsm4(aBaseL + ks*32, al[0], al[1], al[2], al[3]);
            uint32_t bh[8][2], bl[8][2];
            #pragma unroll
            for (int q = 0; q < 4; q++) {
                uint32_t ra = sb + bRowB + (uint32_t)(q*16*PITCH) + bColB + ks*32;
                ldsm4(ra + SM_B_HI, bh[2*q][0], bh[2*q][1], bh[2*q+1][0], bh[2*q+1][1]);
                ldsm4(ra + SM_B_LO, bl[2*q][0], bl[2*q][1], bl[2*q+1][0], bl[2*q+1][1]);
            }
            #pragma unroll
            for (int nc = 0; nc < 8; nc++) {
                mma16816(acc[nc], ah, bh[nc]);
                mma16816(acc[nc], ah, bl[nc]);
                mma16816(acc[nc], al, bh[nc]);
            }
        }
        __syncthreads();
    }

    // ---- epilogue ----
    {
        int ml = m0 + (lane >> 2);
        int nf = (lane & 3) * 2;
        float* obp = out + (size_t)b * COUT * HWSZ + (h << 7) + ml;
        #pragma unroll
        for (int nc = 0; nc < 8; nc++) {
            int n = nc*8 + nf;
            float b0 = __ldg(bias + n), b1 = __ldg(bias + n + 1);
            obp[(size_t)n*HWSZ]         = acc[nc][0] + b0;
            obp[(size_t)(n+1)*HWSZ]     = acc[nc][1] + b1;
            obp[(size_t)n*HWSZ + 8]     = acc[nc][2] + b0;
            obp[(size_t)(n+1)*HWSZ + 8] = acc[nc][3] + b1;
        }
    }
}

// ---------------------------------------------------------------------------
extern "C" void kernel_launch(void* const* d_in, const int* in_sizes, int n_in,
                              void* d_out, int out_size) {
    const float* x    = (const float*)d_in[0];  // [4,64,128,128]
    const float* wt   = (const float*)d_in[1];  // [64,64,3,3]
    const float* bias = (const float*)d_in[2];  // [64]
    const float* owt  = (const float*)d_in[3];  // [27,64,3,3]
    const float* ob   = (const float*)d_in[4];  // [27]
    float* out = (float*)d_out;                 // [4,64,128,128]

    cudaFuncSetAttribute(offset_mma_kernel, cudaFuncAttributeMaxDynamicSharedMemorySize, OSM_TOT);
    cudaFuncSetAttribute(dcn_mma_kernel, cudaFuncAttributeMaxDynamicSharedMemorySize, SM_TOT);

    prep_kernel<<<144, 256>>>(wt, owt);
    offset_mma_kernel<<<512, 256, OSM_TOT>>>(x, ob);
    dcn_mma_kernel<<<512, 256, SM_TOT>>>(x, bias, out);
}